// round 12
// baseline (speedup 1.0000x reference)
#include <cuda_runtime.h>

#define PRED_D 90   // B*5 + C
#define TGT_D 85    // 5 + C
#define THREADS 256
#define NWARPS (THREADS / 32)
#define QSTRIDE (NWARPS * 4)
#define LIST_CAP 768
#define MAXCH 3     // max scan chunks per block (LIST_CAP / THREADS)
#define NBLK 740    // 148 SMs x 5 resident blocks -> exactly one wave

// Accumulators: [0]=xy [1]=wh [2]=conf_obj [3]=conf_noobj [4]=class
__device__ double g_acc[5];
__device__ unsigned int g_done;

// Quarter-warp class load: lane ql (0..7) covers class pairs {2ql,2ql+1}+16k
struct QLd {
    float2 pa[5];
    float  tg[10];
};

__device__ __forceinline__ void load_cls(const float* __restrict__ pred,
                                         const float* __restrict__ tgt,
                                         int cell, int ql, QLd& r)
{
    const long long bp = (long long)cell * PRED_D;
    const long long bt = (long long)cell * TGT_D;
    #pragma unroll
    for (int k = 0; k < 5; k++)
        r.pa[k] = __ldg((const float2*)(pred + bp + 10 + 16 * k + 2 * ql));
    #pragma unroll
    for (int k = 0; k < 5; k++) {
        r.tg[2 * k]     = __ldg(tgt + bt + 5 + 16 * k + 2 * ql);
        r.tg[2 * k + 1] = __ldg(tgt + bt + 6 + 16 * k + 2 * ql);
    }
}

__device__ __forceinline__ float consume_cls(const QLd& r)
{
    float acc = 0.0f;
    #pragma unroll
    for (int k = 0; k < 5; k++) {
        float d0 = r.tg[2 * k]     - r.pa[k].x;
        float d1 = r.tg[2 * k + 1] - r.pa[k].y;
        acc += d0 * d0 + d1 * d1;
    }
    return acc;
}

__device__ __forceinline__ float iou_vs(
    float tx1, float ty1, float tx2, float ty2,
    float px, float py, float pw, float ph,
    float fi, float fj)
{
    const float invS = 1.0f / 7.0f;
    float xc = (px + fj) * invS;
    float yc = (py + fi) * invS;
    float x1 = xc - pw * 0.5f, x2 = xc + pw * 0.5f;
    float y1 = yc - ph * 0.5f, y2 = yc + ph * 0.5f;
    float iw = fmaxf(fminf(tx2, x2) - fmaxf(tx1, x1), 0.0f);
    float ih = fmaxf(fminf(ty2, y2) - fmaxf(ty1, y1), 0.0f);
    float inter = iw * ih;
    float area_a = (tx2 - tx1) * (ty2 - ty1);
    float area_b = (x2 - x1) * (y2 - y1);
    return inter / (area_a + area_b - inter + 1e-6f);
}

__global__ void __launch_bounds__(THREADS, 5)
yolo_loss_kernel(const float* __restrict__ pred,
                 const float* __restrict__ tgt,
                 int ncells, int nblk,
                 float* __restrict__ out, double inv_bs)
{
    __shared__ int   s_list[LIST_CAP];
    __shared__ int   s_cnt;
    __shared__ float s_red[5][NWARPS];
    __shared__ bool  s_last;

    const int tid  = threadIdx.x;
    const int lane = tid & 31;
    const int wid  = tid >> 5;

    if (tid == 0) s_cnt = 0;
    __syncthreads();

    // Static even split: block b covers [start, end)
    const int start = (int)(((long long)blockIdx.x * ncells) / nblk);
    const int end   = (int)(((long long)(blockIdx.x + 1) * ncells) / nblk);

    float a_cn = 0.0f;

    // ---------------- Phase 1: prefetched scan (all loads first) ----------
    {
        float tc_v[MAXCH], pc_v[MAXCH];
        #pragma unroll
        for (int p = 0; p < MAXCH; p++) {
            const int cell = start + p * THREADS + tid;
            tc_v[p] = 0.0f;
            pc_v[p] = 0.0f;
            if (cell < end) {
                tc_v[p] = __ldg(&tgt[(long long)cell * TGT_D + 4]);
                pc_v[p] = __ldg(&pred[(long long)cell * PRED_D + 9]);
            }
        }
        #pragma unroll
        for (int p = 0; p < MAXCH; p++) {
            const int cell = start + p * THREADS + tid;
            bool valid = (cell < end);
            bool isobj = valid && (tc_v[p] != 0.0f);
            if (valid && !isobj) a_cn += pc_v[p] * pc_v[p];

            unsigned int m = __ballot_sync(0xffffffffu, isobj);
            int nwobj = __popc(m);
            int wbase = 0;
            if (lane == 0 && nwobj > 0) wbase = atomicAdd(&s_cnt, nwobj);
            wbase = __shfl_sync(0xffffffffu, wbase, 0);
            if (isobj) {
                int pos = wbase + __popc(m & ((1u << lane) - 1u));
                s_list[pos] = cell;
            }
        }
    }
    __syncthreads();

    const int nobj = s_cnt;

    float a_xy = 0.0f, a_wh = 0.0f, a_co = 0.0f, a_cls = 0.0f;

    // ---------------- Phase 2a: box losses, thread-per-object-cell --------
    // pred row stride 360B (8-aligned) -> float2 OK; tgt 4-aligned -> scalar.
    for (int k = tid; k < nobj; k += THREADS) {
        const int cell = s_list[k];
        const long long bp = (long long)cell * PRED_D;
        const long long bt = (long long)cell * TGT_D;

        float2 b0 = __ldg((const float2*)(pred + bp));       // p0,p1
        float2 b1 = __ldg((const float2*)(pred + bp + 2));   // p2,p3
        float2 b2 = __ldg((const float2*)(pred + bp + 4));   // p4,p5
        float2 b3 = __ldg((const float2*)(pred + bp + 6));   // p6,p7
        float2 b4 = __ldg((const float2*)(pred + bp + 8));   // p8,p9
        float t0 = __ldg(&tgt[bt + 0]);
        float t1 = __ldg(&tgt[bt + 1]);
        float t2 = __ldg(&tgt[bt + 2]);
        float t3 = __ldg(&tgt[bt + 3]);
        float t4 = __ldg(&tgt[bt + 4]);

        const int ij = cell % 49;
        const float fi = (float)(ij / 7);
        const float fj = (float)(ij % 7);

        const float invS = 1.0f / 7.0f;
        float txc = (t0 + fj) * invS;
        float tyc = (t1 + fi) * invS;
        float tx1 = txc - t2 * 0.5f, tx2c = txc + t2 * 0.5f;
        float ty1 = tyc - t3 * 0.5f, ty2c = tyc + t3 * 0.5f;

        float iou0 = iou_vs(tx1, ty1, tx2c, ty2c, b0.x, b0.y, b1.x, b1.y, fi, fj);
        float iou1 = iou_vs(tx1, ty1, tx2c, ty2c, b2.y, b3.x, b3.y, b4.x, fi, fj);

        bool sel = (iou0 > iou1);   // true -> second box
        float sx = sel ? b2.y : b0.x;
        float sy = sel ? b3.x : b0.y;
        float sw = sel ? b3.y : b1.x;
        float sh = sel ? b4.x : b1.y;

        float dx = t0 - sx, dy = t1 - sy;
        a_xy += dx * dx + dy * dy;

        float dw = sqrtf(t2) - sqrtf(fmaxf(sw, 0.0f));
        float dh = sqrtf(t3) - sqrtf(fmaxf(sh, 0.0f));
        a_wh += dw * dw + dh * dh;

        float dc = t4 - b4.y;
        a_co += dc * dc;
    }

    // ---------------- Phase 2b: class loss, quarter-warp-per-cell ---------
    {
        const int qw = lane >> 3;     // quarter-warp id 0..3
        const int ql = lane & 7;      // lane within quarter

        int k = wid * 4 + qw;
        int cell = (k < nobj) ? s_list[k] : -1;
        // hoist next index out of the load dependency chain
        int kn = k + QSTRIDE;
        int ncell_pre = (kn < nobj) ? s_list[kn] : -1;
        QLd cur;
        if (cell >= 0) load_cls(pred, tgt, cell, ql, cur);

        while (cell >= 0) {
            const int ncell = ncell_pre;
            QLd nxt;
            if (ncell >= 0) load_cls(pred, tgt, ncell, ql, nxt);

            // prefetch the index after next while loads are in flight
            int kn2 = kn + QSTRIDE;
            ncell_pre = (kn2 < nobj) ? s_list[kn2] : -1;
            kn = kn2;

            a_cls += consume_cls(cur);

            cur = nxt;
            cell = ncell;
        }
    }

    // ---------------- Reduction ----------------
    #pragma unroll
    for (int off = 16; off > 0; off >>= 1) {
        a_xy  += __shfl_xor_sync(0xffffffffu, a_xy,  off);
        a_wh  += __shfl_xor_sync(0xffffffffu, a_wh,  off);
        a_co  += __shfl_xor_sync(0xffffffffu, a_co,  off);
        a_cn  += __shfl_xor_sync(0xffffffffu, a_cn,  off);
        a_cls += __shfl_xor_sync(0xffffffffu, a_cls, off);
    }

    if (lane == 0) {
        s_red[0][wid] = a_xy;
        s_red[1][wid] = a_wh;
        s_red[2][wid] = a_co;
        s_red[3][wid] = a_cn;
        s_red[4][wid] = a_cls;
    }
    __syncthreads();

    if (tid < 5) {
        double sum = 0.0;
        #pragma unroll
        for (int w = 0; w < NWARPS; w++) sum += (double)s_red[tid][w];
        atomicAdd(&g_acc[tid], sum);
    }
    __syncthreads();

    // ---------------- Last block finalizes + resets ----------------
    if (tid == 0) {
        __threadfence();
        unsigned int t = atomicAdd(&g_done, 1u);
        s_last = (t == gridDim.x - 1);
    }
    __syncthreads();

    if (s_last && tid == 0) {
        __threadfence();
        double lxy  = atomicAdd(&g_acc[0], 0.0) * inv_bs;
        double lwh  = atomicAdd(&g_acc[1], 0.0) * inv_bs;
        double lco  = atomicAdd(&g_acc[2], 0.0) * inv_bs;
        double lcn  = atomicAdd(&g_acc[3], 0.0) * inv_bs;
        double lcls = atomicAdd(&g_acc[4], 0.0) * inv_bs;
        double loss = (5.0 * lxy + 5.0 * lwh + lco + 0.5 * lcn + lcls) * inv_bs;
        out[0] = (float)loss;
        out[1] = (float)lxy;
        out[2] = (float)lwh;
        out[3] = (float)lco;
        out[4] = (float)lcn;
        out[5] = (float)lcls;
        g_acc[0] = 0.0; g_acc[1] = 0.0; g_acc[2] = 0.0;
        g_acc[3] = 0.0; g_acc[4] = 0.0;
        __threadfence();
        g_done = 0u;
    }
}

extern "C" void kernel_launch(void* const* d_in, const int* in_sizes, int n_in,
                              void* d_out, int out_size)
{
    const float* pred = (const float*)d_in[0];
    const float* tgt  = (const float*)d_in[1];
    float* out = (float*)d_out;

    const int N = in_sizes[0] / (49 * PRED_D);
    const int ncells = N * 49;

    // Per-block range must fit the list AND the MAXCH prefetch depth
    int nblk = NBLK;
    int per = (ncells + nblk - 1) / nblk;
    if (per > MAXCH * THREADS) nblk = (ncells + MAXCH * THREADS - 1) / (MAXCH * THREADS);

    yolo_loss_kernel<<<nblk, THREADS>>>(pred, tgt, ncells, nblk, out, 1.0 / (double)N);
}

// round 13
// speedup vs baseline: 1.1015x; 1.1015x over previous
#include <cuda_runtime.h>

#define PRED_D 90   // B*5 + C
#define TGT_D 85    // 5 + C
#define THREADS 256
#define NWARPS (THREADS / 32)
#define NC 3                    // cells per stage per warp
#define CSTRIDE (NWARPS * NC)   // 24
#define LIST_CAP 768
#define NBLK 740    // 148 SMs x 5 resident blocks -> one wave

// Accumulators: [0]=xy [1]=wh [2]=conf_obj [3]=conf_noobj [4]=class
__device__ double g_acc[5];
__device__ unsigned int g_done;

__device__ __forceinline__ void cpa8(unsigned dst, const void* src) {
    asm volatile("cp.async.ca.shared.global [%0], [%1], 8;\n" :: "r"(dst), "l"(src));
}
__device__ __forceinline__ void cpa4(unsigned dst, const void* src) {
    asm volatile("cp.async.ca.shared.global [%0], [%1], 4;\n" :: "r"(dst), "l"(src));
}
__device__ __forceinline__ void cp_commit() {
    asm volatile("cp.async.commit_group;\n" ::: "memory");
}
template<int N> __device__ __forceinline__ void cp_wait() {
    asm volatile("cp.async.wait_group %0;\n" :: "n"(N) : "memory");
}

__device__ __forceinline__ float iou_vs(
    float tx1, float ty1, float tx2, float ty2,
    float px, float py, float pw, float ph,
    float fi, float fj)
{
    const float invS = 1.0f / 7.0f;
    float xc = (px + fj) * invS;
    float yc = (py + fi) * invS;
    float x1 = xc - pw * 0.5f, x2 = xc + pw * 0.5f;
    float y1 = yc - ph * 0.5f, y2 = yc + ph * 0.5f;
    float iw = fmaxf(fminf(tx2, x2) - fmaxf(tx1, x1), 0.0f);
    float ih = fmaxf(fminf(ty2, y2) - fmaxf(ty1, y1), 0.0f);
    float inter = iw * ih;
    float area_a = (tx2 - tx1) * (ty2 - ty1);
    float area_b = (x2 - x1) * (y2 - y1);
    return inter / (area_a + area_b - inter + 1e-6f);
}

__global__ void __launch_bounds__(THREADS)
yolo_loss_kernel(const float* __restrict__ pred,
                 const float* __restrict__ tgt,
                 int ncells, int nblk,
                 float* __restrict__ out, double inv_bs)
{
    // Per-warp double-buffered class staging: [warp][stage][NC cells x 160 floats]
    // layout per cell: floats [0..79] = pred class, [80..159] = tgt class
    __shared__ float s_cls[NWARPS][2][NC * 160];
    __shared__ int   s_list[LIST_CAP];
    __shared__ int   s_cnt;
    __shared__ float s_red[5][NWARPS];
    __shared__ bool  s_last;

    const int tid  = threadIdx.x;
    const int lane = tid & 31;
    const int wid  = tid >> 5;

    if (tid == 0) s_cnt = 0;
    __syncthreads();

    // Static even split: block b covers [start, end)
    const int start = (int)(((long long)blockIdx.x * ncells) / nblk);
    const int end   = (int)(((long long)(blockIdx.x + 1) * ncells) / nblk);

    float a_cn = 0.0f;

    // ---------------- Phase 1: barrier-free scan (exactly R11) ------------
    for (int base = start; base < end; base += THREADS) {
        const int cell = base + tid;
        float tc = 0.0f, pc = 0.0f;
        bool valid = (cell < end);
        if (valid) {
            tc = __ldg(&tgt[(long long)cell * TGT_D + 4]);
            pc = __ldg(&pred[(long long)cell * PRED_D + 9]);
        }
        bool isobj = valid && (tc != 0.0f);
        if (valid && !isobj) a_cn += pc * pc;

        unsigned int m = __ballot_sync(0xffffffffu, isobj);
        int nwobj = __popc(m);
        int wbase = 0;
        if (lane == 0 && nwobj > 0) wbase = atomicAdd(&s_cnt, nwobj);
        wbase = __shfl_sync(0xffffffffu, wbase, 0);
        if (isobj) {
            int pos = wbase + __popc(m & ((1u << lane) - 1u));
            s_list[pos] = cell;
        }
    }
    __syncthreads();

    const int nobj = s_cnt;

    float a_xy = 0.0f, a_wh = 0.0f, a_co = 0.0f, a_cls = 0.0f;

    // ---------------- Phase 2a: box losses, thread-per-object-cell --------
    for (int k = tid; k < nobj; k += THREADS) {
        const int cell = s_list[k];
        const long long bp = (long long)cell * PRED_D;
        const long long bt = (long long)cell * TGT_D;

        float2 b0 = __ldg((const float2*)(pred + bp));       // p0,p1
        float2 b1 = __ldg((const float2*)(pred + bp + 2));   // p2,p3
        float2 b2 = __ldg((const float2*)(pred + bp + 4));   // p4,p5
        float2 b3 = __ldg((const float2*)(pred + bp + 6));   // p6,p7
        float2 b4 = __ldg((const float2*)(pred + bp + 8));   // p8,p9
        float t0 = __ldg(&tgt[bt + 0]);
        float t1 = __ldg(&tgt[bt + 1]);
        float t2 = __ldg(&tgt[bt + 2]);
        float t3 = __ldg(&tgt[bt + 3]);
        float t4 = __ldg(&tgt[bt + 4]);

        const int ij = cell % 49;
        const float fi = (float)(ij / 7);
        const float fj = (float)(ij % 7);

        const float invS = 1.0f / 7.0f;
        float txc = (t0 + fj) * invS;
        float tyc = (t1 + fi) * invS;
        float tx1 = txc - t2 * 0.5f, tx2c = txc + t2 * 0.5f;
        float ty1 = tyc - t3 * 0.5f, ty2c = tyc + t3 * 0.5f;

        float iou0 = iou_vs(tx1, ty1, tx2c, ty2c, b0.x, b0.y, b1.x, b1.y, fi, fj);
        float iou1 = iou_vs(tx1, ty1, tx2c, ty2c, b2.y, b3.x, b3.y, b4.x, fi, fj);

        bool sel = (iou0 > iou1);   // true -> second box
        float sx = sel ? b2.y : b0.x;
        float sy = sel ? b3.x : b0.y;
        float sw = sel ? b3.y : b1.x;
        float sh = sel ? b4.x : b1.y;

        float dx = t0 - sx, dy = t1 - sy;
        a_xy += dx * dx + dy * dy;

        float dw = sqrtf(t2) - sqrtf(fmaxf(sw, 0.0f));
        float dh = sqrtf(t3) - sqrtf(fmaxf(sh, 0.0f));
        a_wh += dw * dw + dh * dh;

        float dc = t4 - b4.y;
        a_co += dc * dc;
    }

    // ------- Phase 2b: class loss, warp-private cp.async double buffer -----
    {
        float* buf0 = s_cls[wid][0];
        float* buf1 = s_cls[wid][1];
        const int k0 = wid * NC;

        // gather NC cells' class data (pred 40x8B, tgt 80x4B per cell)
        auto gather = [&](float* buf, int kb) {
            #pragma unroll
            for (int c = 0; c < NC; c++) {
                if (kb + c < nobj) {
                    const int cell = s_list[kb + c];
                    const float* ps = pred + (long long)cell * PRED_D + 10; // 8B-aligned
                    const float* ts = tgt  + (long long)cell * TGT_D + 5;   // 4B-aligned
                    unsigned d8 = (unsigned)__cvta_generic_to_shared(buf + c * 160);
                    unsigned d4 = d8 + 320;
                    cpa8(d8 + lane * 8, ps + lane * 2);
                    if (lane < 8)  cpa8(d8 + (32 + lane) * 8, ps + (32 + lane) * 2);
                    cpa4(d4 + lane * 4, ts + lane);
                    cpa4(d4 + (32 + lane) * 4, ts + 32 + lane);
                    if (lane < 16) cpa4(d4 + (64 + lane) * 4, ts + 64 + lane);
                }
            }
            cp_commit();
        };

        gather(buf0, k0);
        gather(buf1, k0 + CSTRIDE);

        int it = 0;
        for (int k = k0; k < nobj; k += CSTRIDE, it++) {
            cp_wait<1>();
            __syncwarp();
            float* buf = (it & 1) ? buf1 : buf0;
            #pragma unroll
            for (int c = 0; c < NC; c++) {
                if (k + c < nobj) {
                    const float* row = buf + c * 160;
                    float d0 = row[80 + lane]  - row[lane];
                    float d1 = row[112 + lane] - row[32 + lane];
                    a_cls += d0 * d0 + d1 * d1;
                    if (lane < 16) {
                        float d2 = row[144 + lane] - row[64 + lane];
                        a_cls += d2 * d2;
                    }
                }
            }
            __syncwarp();
            gather(buf, k + 2 * CSTRIDE);
        }
        cp_wait<0>();
        __syncwarp();
    }

    // ---------------- Reduction ----------------
    #pragma unroll
    for (int off = 16; off > 0; off >>= 1) {
        a_xy  += __shfl_xor_sync(0xffffffffu, a_xy,  off);
        a_wh  += __shfl_xor_sync(0xffffffffu, a_wh,  off);
        a_co  += __shfl_xor_sync(0xffffffffu, a_co,  off);
        a_cn  += __shfl_xor_sync(0xffffffffu, a_cn,  off);
        a_cls += __shfl_xor_sync(0xffffffffu, a_cls, off);
    }

    if (lane == 0) {
        s_red[0][wid] = a_xy;
        s_red[1][wid] = a_wh;
        s_red[2][wid] = a_co;
        s_red[3][wid] = a_cn;
        s_red[4][wid] = a_cls;
    }
    __syncthreads();

    if (tid < 5) {
        double sum = 0.0;
        #pragma unroll
        for (int w = 0; w < NWARPS; w++) sum += (double)s_red[tid][w];
        atomicAdd(&g_acc[tid], sum);
    }
    __syncthreads();

    // ---------------- Last block finalizes + resets ----------------
    if (tid == 0) {
        __threadfence();
        unsigned int t = atomicAdd(&g_done, 1u);
        s_last = (t == gridDim.x - 1);
    }
    __syncthreads();

    if (s_last && tid == 0) {
        __threadfence();
        double lxy  = atomicAdd(&g_acc[0], 0.0) * inv_bs;
        double lwh  = atomicAdd(&g_acc[1], 0.0) * inv_bs;
        double lco  = atomicAdd(&g_acc[2], 0.0) * inv_bs;
        double lcn  = atomicAdd(&g_acc[3], 0.0) * inv_bs;
        double lcls = atomicAdd(&g_acc[4], 0.0) * inv_bs;
        double loss = (5.0 * lxy + 5.0 * lwh + lco + 0.5 * lcn + lcls) * inv_bs;
        out[0] = (float)loss;
        out[1] = (float)lxy;
        out[2] = (float)lwh;
        out[3] = (float)lco;
        out[4] = (float)lcn;
        out[5] = (float)lcls;
        g_acc[0] = 0.0; g_acc[1] = 0.0; g_acc[2] = 0.0;
        g_acc[3] = 0.0; g_acc[4] = 0.0;
        __threadfence();
        g_done = 0u;
    }
}

extern "C" void kernel_launch(void* const* d_in, const int* in_sizes, int n_in,
                              void* d_out, int out_size)
{
    const float* pred = (const float*)d_in[0];
    const float* tgt  = (const float*)d_in[1];
    float* out = (float*)d_out;

    const int N = in_sizes[0] / (49 * PRED_D);
    const int ncells = N * 49;

    // Per-block range must fit the object list
    int nblk = NBLK;
    int per = (ncells + nblk - 1) / nblk;
    if (per > LIST_CAP) nblk = (ncells + LIST_CAP - 1) / LIST_CAP;

    yolo_loss_kernel<<<nblk, THREADS>>>(pred, tgt, ncells, nblk, out, 1.0 / (double)N);
}

// round 14
// speedup vs baseline: 1.2452x; 1.1304x over previous
#include <cuda_runtime.h>

#define PRED_D 90   // B*5 + C
#define TGT_D 85    // 5 + C
#define THREADS 256
#define NWARPS (THREADS / 32)
#define QSTRIDE (NWARPS * 4)
#define LIST_CAP 768
#define MAXCH 3     // max scan chunks per block
#define NBLK 740    // 148 SMs x 5 resident blocks -> exactly one wave

// Accumulators: [0]=xy [1]=wh [2]=conf_obj [3]=conf_noobj [4]=class
__device__ double g_acc[5];
__device__ unsigned int g_done;

// Quarter-warp class load: lane ql (0..7) covers class pairs {2ql,2ql+1}+16k
struct QLd {
    float2 pa[5];
    float  tg[10];
};

__device__ __forceinline__ void load_cls(const float* __restrict__ pred,
                                         const float* __restrict__ tgt,
                                         int cell, int ql, QLd& r)
{
    const long long bp = (long long)cell * PRED_D;
    const long long bt = (long long)cell * TGT_D;
    #pragma unroll
    for (int k = 0; k < 5; k++)
        r.pa[k] = __ldg((const float2*)(pred + bp + 10 + 16 * k + 2 * ql));
    #pragma unroll
    for (int k = 0; k < 5; k++) {
        r.tg[2 * k]     = __ldg(tgt + bt + 5 + 16 * k + 2 * ql);
        r.tg[2 * k + 1] = __ldg(tgt + bt + 6 + 16 * k + 2 * ql);
    }
}

__device__ __forceinline__ float consume_cls(const QLd& r)
{
    float acc = 0.0f;
    #pragma unroll
    for (int k = 0; k < 5; k++) {
        float d0 = r.tg[2 * k]     - r.pa[k].x;
        float d1 = r.tg[2 * k + 1] - r.pa[k].y;
        acc += d0 * d0 + d1 * d1;
    }
    return acc;
}

__device__ __forceinline__ float iou_vs(
    float tx1, float ty1, float tx2, float ty2,
    float px, float py, float pw, float ph,
    float fi, float fj)
{
    const float invS = 1.0f / 7.0f;
    float xc = (px + fj) * invS;
    float yc = (py + fi) * invS;
    float x1 = xc - pw * 0.5f, x2 = xc + pw * 0.5f;
    float y1 = yc - ph * 0.5f, y2 = yc + ph * 0.5f;
    float iw = fmaxf(fminf(tx2, x2) - fmaxf(tx1, x1), 0.0f);
    float ih = fmaxf(fminf(ty2, y2) - fmaxf(ty1, y1), 0.0f);
    float inter = iw * ih;
    float area_a = (tx2 - tx1) * (ty2 - ty1);
    float area_b = (x2 - x1) * (y2 - y1);
    return inter / (area_a + area_b - inter + 1e-6f);
}

__global__ void __launch_bounds__(THREADS)
yolo_loss_kernel(const float* __restrict__ pred,
                 const float* __restrict__ tgt,
                 int ncells, int nblk,
                 float* __restrict__ out, double inv_bs)
{
    __shared__ int   s_list[LIST_CAP];
    __shared__ int   s_cnt;
    __shared__ float s_red[5][NWARPS];
    __shared__ bool  s_last;

    const int tid  = threadIdx.x;
    const int lane = tid & 31;
    const int wid  = tid >> 5;

    if (tid == 0) s_cnt = 0;
    __syncthreads();

    // Static even split: block b covers [start, end)
    const int start = (int)(((long long)blockIdx.x * ncells) / nblk);
    const int end   = (int)(((long long)(blockIdx.x + 1) * ncells) / nblk);

    float a_cn = 0.0f;

    // ---------------- Phase 1: prefetched scan (all loads up front) -------
    {
        float tc_v[MAXCH], pc_v[MAXCH];
        #pragma unroll
        for (int p = 0; p < MAXCH; p++) {
            const int cell = start + p * THREADS + tid;
            tc_v[p] = 0.0f;
            pc_v[p] = 0.0f;
            if (cell < end) {
                tc_v[p] = __ldg(&tgt[(long long)cell * TGT_D + 4]);
                pc_v[p] = __ldg(&pred[(long long)cell * PRED_D + 9]);
            }
        }
        #pragma unroll
        for (int p = 0; p < MAXCH; p++) {
            const int cell = start + p * THREADS + tid;
            bool valid = (cell < end);
            bool isobj = valid && (tc_v[p] != 0.0f);
            if (valid && !isobj) a_cn += pc_v[p] * pc_v[p];

            unsigned int m = __ballot_sync(0xffffffffu, isobj);
            int nwobj = __popc(m);
            int wbase = 0;
            if (lane == 0 && nwobj > 0) wbase = atomicAdd(&s_cnt, nwobj);
            wbase = __shfl_sync(0xffffffffu, wbase, 0);
            if (isobj) {
                int pos = wbase + __popc(m & ((1u << lane) - 1u));
                s_list[pos] = cell;
            }
        }
    }
    __syncthreads();

    const int nobj = s_cnt;

    float a_xy = 0.0f, a_wh = 0.0f, a_co = 0.0f, a_cls = 0.0f;

    // ---------------- Phase 2a: box losses, thread-per-object-cell --------
    // pred row stride 360B (8-aligned) -> float2 OK; tgt 4-aligned -> scalar.
    for (int k = tid; k < nobj; k += THREADS) {
        const int cell = s_list[k];
        const long long bp = (long long)cell * PRED_D;
        const long long bt = (long long)cell * TGT_D;

        float2 b0 = __ldg((const float2*)(pred + bp));       // p0,p1
        float2 b1 = __ldg((const float2*)(pred + bp + 2));   // p2,p3
        float2 b2 = __ldg((const float2*)(pred + bp + 4));   // p4,p5
        float2 b3 = __ldg((const float2*)(pred + bp + 6));   // p6,p7
        float2 b4 = __ldg((const float2*)(pred + bp + 8));   // p8,p9
        float t0 = __ldg(&tgt[bt + 0]);
        float t1 = __ldg(&tgt[bt + 1]);
        float t2 = __ldg(&tgt[bt + 2]);
        float t3 = __ldg(&tgt[bt + 3]);
        float t4 = __ldg(&tgt[bt + 4]);

        const int ij = cell % 49;
        const float fi = (float)(ij / 7);
        const float fj = (float)(ij % 7);

        const float invS = 1.0f / 7.0f;
        float txc = (t0 + fj) * invS;
        float tyc = (t1 + fi) * invS;
        float tx1 = txc - t2 * 0.5f, tx2c = txc + t2 * 0.5f;
        float ty1 = tyc - t3 * 0.5f, ty2c = tyc + t3 * 0.5f;

        float iou0 = iou_vs(tx1, ty1, tx2c, ty2c, b0.x, b0.y, b1.x, b1.y, fi, fj);
        float iou1 = iou_vs(tx1, ty1, tx2c, ty2c, b2.y, b3.x, b3.y, b4.x, fi, fj);

        bool sel = (iou0 > iou1);   // true -> second box
        float sx = sel ? b2.y : b0.x;
        float sy = sel ? b3.x : b0.y;
        float sw = sel ? b3.y : b1.x;
        float sh = sel ? b4.x : b1.y;

        float dx = t0 - sx, dy = t1 - sy;
        a_xy += dx * dx + dy * dy;

        float dw = sqrtf(t2) - sqrtf(fmaxf(sw, 0.0f));
        float dh = sqrtf(t3) - sqrtf(fmaxf(sh, 0.0f));
        a_wh += dw * dw + dh * dh;

        float dc = t4 - b4.y;
        a_co += dc * dc;
    }

    // ---------------- Phase 2b: class loss, quarter-warp-per-cell ---------
    {
        const int qw = lane >> 3;     // quarter-warp id 0..3
        const int ql = lane & 7;      // lane within quarter

        int k = wid * 4 + qw;
        int cell = (k < nobj) ? s_list[k] : -1;
        QLd cur;
        if (cell >= 0) load_cls(pred, tgt, cell, ql, cur);

        while (cell >= 0) {
            int kn = k + QSTRIDE;
            int ncell = (kn < nobj) ? s_list[kn] : -1;
            QLd nxt;
            if (ncell >= 0) load_cls(pred, tgt, ncell, ql, nxt);

            a_cls += consume_cls(cur);

            cur = nxt;
            cell = ncell;
            k = kn;
        }
    }

    // ---------------- Reduction ----------------
    #pragma unroll
    for (int off = 16; off > 0; off >>= 1) {
        a_xy  += __shfl_xor_sync(0xffffffffu, a_xy,  off);
        a_wh  += __shfl_xor_sync(0xffffffffu, a_wh,  off);
        a_co  += __shfl_xor_sync(0xffffffffu, a_co,  off);
        a_cn  += __shfl_xor_sync(0xffffffffu, a_cn,  off);
        a_cls += __shfl_xor_sync(0xffffffffu, a_cls, off);
    }

    if (lane == 0) {
        s_red[0][wid] = a_xy;
        s_red[1][wid] = a_wh;
        s_red[2][wid] = a_co;
        s_red[3][wid] = a_cn;
        s_red[4][wid] = a_cls;
    }
    __syncthreads();

    if (tid < 5) {
        double sum = 0.0;
        #pragma unroll
        for (int w = 0; w < NWARPS; w++) sum += (double)s_red[tid][w];
        atomicAdd(&g_acc[tid], sum);
    }
    __syncthreads();

    // ---------------- Last block finalizes + resets ----------------
    if (tid == 0) {
        __threadfence();
        unsigned int t = atomicAdd(&g_done, 1u);
        s_last = (t == gridDim.x - 1);
    }
    __syncthreads();

    if (s_last && tid == 0) {
        __threadfence();
        double lxy  = atomicAdd(&g_acc[0], 0.0) * inv_bs;
        double lwh  = atomicAdd(&g_acc[1], 0.0) * inv_bs;
        double lco  = atomicAdd(&g_acc[2], 0.0) * inv_bs;
        double lcn  = atomicAdd(&g_acc[3], 0.0) * inv_bs;
        double lcls = atomicAdd(&g_acc[4], 0.0) * inv_bs;
        double loss = (5.0 * lxy + 5.0 * lwh + lco + 0.5 * lcn + lcls) * inv_bs;
        out[0] = (float)loss;
        out[1] = (float)lxy;
        out[2] = (float)lwh;
        out[3] = (float)lco;
        out[4] = (float)lcn;
        out[5] = (float)lcls;
        g_acc[0] = 0.0; g_acc[1] = 0.0; g_acc[2] = 0.0;
        g_acc[3] = 0.0; g_acc[4] = 0.0;
        __threadfence();
        g_done = 0u;
    }
}

extern "C" void kernel_launch(void* const* d_in, const int* in_sizes, int n_in,
                              void* d_out, int out_size)
{
    const float* pred = (const float*)d_in[0];
    const float* tgt  = (const float*)d_in[1];
    float* out = (float*)d_out;

    const int N = in_sizes[0] / (49 * PRED_D);
    const int ncells = N * 49;

    // Per-block range must fit the list AND the MAXCH prefetch depth
    int nblk = NBLK;
    int per = (ncells + nblk - 1) / nblk;
    if (per > MAXCH * THREADS) nblk = (ncells + MAXCH * THREADS - 1) / (MAXCH * THREADS);

    yolo_loss_kernel<<<nblk, THREADS>>>(pred, tgt, ncells, nblk, out, 1.0 / (double)N);
}